// round 14
// baseline (speedup 1.0000x reference)
#include <cuda_runtime.h>
#include <cstdint>
#include <math.h>

#define BETA  5.5f
#define NC    1000
#define NM    50
#define ND    1024
#define ND4   256
#define QB    100        // qn partial blocks (10 rows each)
#define QROWS 10
#define GRID  296        // persistent CTAs (2/SM x 148; <= GB300 capacity)

__device__ __align__(16) float g_qn[ND];
__device__ float g_logits[NC];
__device__ float g_qpart[QB * ND];
__device__ unsigned int g_qtick = 0;
__device__ unsigned int g_qflag = 0;
__device__ unsigned int g_work  = 0;
__device__ unsigned int g_done  = 0;

// ---------------------------------------------------------------------------
// Single persistent kernel: fused qn + per-class attention + softmax.
// grid=296, block=128 (4 warps). Mainloop is the round-3/13 proven optimum
// (warp-per-row, register double buffer, barrier-free).
// ---------------------------------------------------------------------------
__global__ void __launch_bounds__(128)
dualmem_kernel(const float* __restrict__ mem,
               const float* __restrict__ van,
               const float* __restrict__ gbk,
               const float* __restrict__ gbv,
               const float* __restrict__ ffn,
               const float* __restrict__ img,
               const float* __restrict__ gb,
               const float* __restrict__ scale,
               float* __restrict__ out)
{
    const int bid  = blockIdx.x;
    const int t    = threadIdx.x;       // 0..127
    const int wi   = t >> 5;
    const int lane = t & 31;

    __shared__ float4 qn_s[ND4];
    __shared__ float4 bk_s[ND4];
    __shared__ float4 bv_s[ND4];
    __shared__ float4 accs[4][ND4];
    __shared__ float  sw_s[4];
    __shared__ float4 redc[4];
    __shared__ float  red1[4];
    __shared__ float2 red2[4];
    __shared__ float  redm[4], reds[4];
    __shared__ unsigned int utick;
    __shared__ int cur_c;

    // ===================== phase 0: fused qn =====================
    if (bid < QB) {
        // partial column sums of 10 gb rows; thread t owns cols t+128k
        #pragma unroll
        for (int k = 0; k < 8; ++k) {
            const int d = t + k * 128;
            const float* base = gb + (size_t)bid * QROWS * ND + d;
            float s = 0.0f;
            #pragma unroll
            for (int r = 0; r < QROWS; ++r) s += base[r * ND];
            g_qpart[bid * ND + d] = s;
        }
        __threadfence();
        __syncthreads();
        if (t == 0) utick = atomicAdd(&g_qtick, 1u);
        __syncthreads();
        if (utick == QB - 1) {
            // finisher: sum partials, add img, l2norm, publish flag
            float q[8];
            float ss = 0.0f;
            #pragma unroll
            for (int k = 0; k < 8; ++k) {
                const int d = t + k * 128;
                float s = 0.0f;
                #pragma unroll 4
                for (int b = 0; b < QB; ++b) s += g_qpart[b * ND + d];
                q[k] = img[d] + s * (1.0f / (float)NC);
                ss += q[k] * q[k];
            }
            #pragma unroll
            for (int o = 16; o; o >>= 1) ss += __shfl_xor_sync(0xffffffffu, ss, o);
            if (lane == 0) red1[wi] = ss;
            __syncthreads();
            const float tot = red1[0] + red1[1] + red1[2] + red1[3];
            const float rq  = rsqrtf(tot);
            #pragma unroll
            for (int k = 0; k < 8; ++k) g_qn[t + k * 128] = q[k] * rq;
            __threadfence();
            if (t == 0) atomicExch(&g_qflag, 1u);
        }
    }

    // all CTAs: wait for qn
    if (t == 0) {
        while (atomicAdd(&g_qflag, 0u) == 0u) __nanosleep(200);
        __threadfence();
    }
    __syncthreads();

    // ===================== phase 1: class work loop =====================
    while (true) {
        __syncthreads();                 // protect smem reuse + cur_c
        if (t == 0) cur_c = (int)atomicAdd(&g_work, 1u);
        __syncthreads();
        const int c = cur_c;
        if (c >= NC) break;

        const float4* qn4  = (const float4*)g_qn;
        const float4* gbk4 = (const float4*)(gbk + (size_t)c * ND);
        const float4* gbv4 = (const float4*)(gbv + (size_t)c * ND);
        const float4* mem4 = (const float4*)(mem + (size_t)c * NM * ND);
        const float4* van4 = (const float4*)(van + (size_t)c * ND);

        // --- prologue: stage qn/bk/bv, per-class constants ---
        float pqk = 0.0f, pkk = 0.0f, pvv = 0.0f;
        #pragma unroll
        for (int r = 0; r < 2; ++r) {
            const int idx = t + r * 128;
            const float4 q = __ldcg(&qn4[idx]);   // L2 read (flag-published data)
            const float4 k = gbk4[idx];
            const float4 v = gbv4[idx];
            qn_s[idx] = q; bk_s[idx] = k; bv_s[idx] = v;
            pqk += q.x*k.x + q.y*k.y + q.z*k.z + q.w*k.w;
            pkk += k.x*k.x + k.y*k.y + k.z*k.z + k.w*k.w;
            pvv += v.x*v.x + v.y*v.y + v.z*v.z + v.w*v.w;
        }
        #pragma unroll
        for (int o = 16; o; o >>= 1) {
            pqk += __shfl_xor_sync(0xffffffffu, pqk, o);
            pkk += __shfl_xor_sync(0xffffffffu, pkk, o);
            pvv += __shfl_xor_sync(0xffffffffu, pvv, o);
        }
        if (lane == 0) redc[wi] = make_float4(pqk, pkk, pvv, 0.0f);
        __syncthreads();
        float qk_c = 0.0f, kk_c = 0.0f, vv_c = 0.0f;
        #pragma unroll
        for (int i = 0; i < 4; ++i) {
            qk_c += redc[i].x; kk_c += redc[i].y; vv_c += redc[i].z;
        }

        // --- mainloop: warp wi handles rows wi, wi+4, ... (row 50 = vanilla) ---
        float4 acc[8];
        #pragma unroll
        for (int j = 0; j < 8; ++j) acc[j] = make_float4(0.f, 0.f, 0.f, 0.f);
        float sw = 0.0f;

        float4 xr[8], xn[8];
        {
            const float4* rp = (wi < NM) ? (mem4 + (size_t)wi * ND4) : van4;
            #pragma unroll
            for (int j = 0; j < 8; ++j) xr[j] = rp[j * 32 + lane];
        }

        int m = wi;
        while (true) {
            const int  mn = m + 4;
            const bool hn = (mn <= NM);
            if (hn) {
                const float4* rq = (mn < NM) ? (mem4 + (size_t)mn * ND4) : van4;
                #pragma unroll
                for (int j = 0; j < 8; ++j) xn[j] = rq[j * 32 + lane];
            }

            float xx = 0.0f, qx = 0.0f, xk = 0.0f, xv = 0.0f;
            #pragma unroll
            for (int j = 0; j < 8; ++j) {
                const float4 x = xr[j];
                const float4 q = qn_s[j * 32 + lane];
                const float4 k = bk_s[j * 32 + lane];
                const float4 v = bv_s[j * 32 + lane];
                xx += x.x*x.x + x.y*x.y + x.z*x.z + x.w*x.w;
                qx += q.x*x.x + q.y*x.y + q.z*x.z + q.w*x.w;
                xk += k.x*x.x + k.y*x.y + k.z*x.z + k.w*x.w;
                xv += v.x*x.x + v.y*x.y + v.z*x.z + v.w*x.w;
            }
            #pragma unroll
            for (int o = 16; o; o >>= 1) {
                xx += __shfl_xor_sync(0xffffffffu, xx, o);
                qx += __shfl_xor_sync(0xffffffffu, qx, o);
                xk += __shfl_xor_sync(0xffffffffu, xk, o);
                xv += __shfl_xor_sync(0xffffffffu, xv, o);
            }

            float w = 0.0f;
            if (xx != 0.0f) {              // all-zero row <=> |x|^2 == 0
                const float dq = qx + qk_c;
                const float k2 = xx + 2.0f * xk + kk_c;
                const float v2 = xx + 2.0f * xv + vv_c;
                w = __expf(-BETA * (1.0f - dq * rsqrtf(k2))) * rsqrtf(v2);
            }
            sw += w;
            #pragma unroll
            for (int j = 0; j < 8; ++j) {
                acc[j].x += w * xr[j].x;
                acc[j].y += w * xr[j].y;
                acc[j].z += w * xr[j].z;
                acc[j].w += w * xr[j].w;
            }

            if (!hn) break;
            #pragma unroll
            for (int j = 0; j < 8; ++j) xr[j] = xn[j];
            m = mn;
        }

        // --- combine warps: acc_total = sum_w acc + sw_total * bv ---
        #pragma unroll
        for (int j = 0; j < 8; ++j) accs[wi][j * 32 + lane] = acc[j];
        if (lane == 0) sw_s[wi] = sw;
        __syncthreads();

        const float swt = sw_s[0] + sw_s[1] + sw_s[2] + sw_s[3];
        float4 a0, a1;
        {
            const int i0 = t, i1 = t + 128;
            float4 s0 = accs[0][i0], s1 = accs[0][i1];
            #pragma unroll
            for (int w = 1; w < 4; ++w) {
                const float4 p = accs[w][i0], q = accs[w][i1];
                s0.x += p.x; s0.y += p.y; s0.z += p.z; s0.w += p.w;
                s1.x += q.x; s1.y += q.y; s1.z += q.z; s1.w += q.w;
            }
            const float4 b0 = bv_s[i0], b1 = bv_s[i1];
            a0 = make_float4(s0.x + swt*b0.x, s0.y + swt*b0.y, s0.z + swt*b0.z, s0.w + swt*b0.w);
            a1 = make_float4(s1.x + swt*b1.x, s1.y + swt*b1.y, s1.z + swt*b1.z, s1.w + swt*b1.w);
        }

        // l2norm(acc)
        float n1 = a0.x*a0.x + a0.y*a0.y + a0.z*a0.z + a0.w*a0.w
                 + a1.x*a1.x + a1.y*a1.y + a1.z*a1.z + a1.w*a1.w;
        #pragma unroll
        for (int o = 16; o; o >>= 1) n1 += __shfl_xor_sync(0xffffffffu, n1, o);
        if (lane == 0) red1[wi] = n1;
        __syncthreads();
        const float rin1 = rsqrtf(red1[0] + red1[1] + red1[2] + red1[3]);

        // + ffn, l2norm, dot img
        const float4* ffn4 = (const float4*)(ffn + (size_t)c * ND);
        const float4* img4 = (const float4*)img;
        const float4 f0 = ffn4[t], f1 = ffn4[t + 128];
        const float4 i0 = img4[t], i1 = img4[t + 128];
        const float4 af0 = make_float4(a0.x*rin1 + f0.x, a0.y*rin1 + f0.y,
                                       a0.z*rin1 + f0.z, a0.w*rin1 + f0.w);
        const float4 af1 = make_float4(a1.x*rin1 + f1.x, a1.y*rin1 + f1.y,
                                       a1.z*rin1 + f1.z, a1.w*rin1 + f1.w);

        float n2 = af0.x*af0.x + af0.y*af0.y + af0.z*af0.z + af0.w*af0.w
                 + af1.x*af1.x + af1.y*af1.y + af1.z*af1.z + af1.w*af1.w;
        float dp = af0.x*i0.x + af0.y*i0.y + af0.z*i0.z + af0.w*i0.w
                 + af1.x*i1.x + af1.y*i1.y + af1.z*i1.z + af1.w*i1.w;
        #pragma unroll
        for (int o = 16; o; o >>= 1) {
            n2 += __shfl_xor_sync(0xffffffffu, n2, o);
            dp += __shfl_xor_sync(0xffffffffu, dp, o);
        }
        if (lane == 0) red2[wi] = make_float2(n2, dp);
        __syncthreads();

        if (t == 0) {
            float n2t = 0.0f, dpt = 0.0f;
            #pragma unroll
            for (int i = 0; i < 4; ++i) { n2t += red2[i].x; dpt += red2[i].y; }
            g_logits[c] = expf(scale[0]) * dpt * rsqrtf(n2t);
        }
    }

    // ===================== phase 2: done ticket + softmax =====================
    __threadfence();
    __syncthreads();
    if (t == 0) utick = atomicAdd(&g_done, 1u);
    __syncthreads();
    if (utick != GRID - 1) return;

    float x[8];
    #pragma unroll
    for (int k = 0; k < 8; ++k) {
        const int i = t + k * 128;
        x[k] = (i < NC) ? g_logits[i] : -INFINITY;
    }
    float mx = x[0];
    #pragma unroll
    for (int k = 1; k < 8; ++k) mx = fmaxf(mx, x[k]);
    #pragma unroll
    for (int o = 16; o; o >>= 1) mx = fmaxf(mx, __shfl_xor_sync(0xffffffffu, mx, o));
    if (lane == 0) redm[wi] = mx;
    __syncthreads();
    mx = fmaxf(fmaxf(redm[0], redm[1]), fmaxf(redm[2], redm[3]));

    float e[8];
    float es = 0.0f;
    #pragma unroll
    for (int k = 0; k < 8; ++k) {
        const int i = t + k * 128;
        e[k] = (i < NC) ? expf(x[k] - mx) : 0.0f;
        es += e[k];
    }
    #pragma unroll
    for (int o = 16; o; o >>= 1) es += __shfl_xor_sync(0xffffffffu, es, o);
    if (lane == 0) reds[wi] = es;
    __syncthreads();
    const float rst = 1.0f / (reds[0] + reds[1] + reds[2] + reds[3]);

    #pragma unroll
    for (int k = 0; k < 8; ++k) {
        const int i = t + k * 128;
        if (i < NC) out[i] = e[k] * rst;
    }
    if (t == 0) {                        // reset for graph replay (race-free:
        g_work = 0; g_done = 0;          // no CTA touches these after its
        g_qflag = 0; g_qtick = 0;        // done-bump, and this is the last)
    }
}

// ---------------------------------------------------------------------------
extern "C" void kernel_launch(void* const* d_in, const int* in_sizes, int n_in,
                              void* d_out, int out_size)
{
    const float* img   = (const float*)d_in[0];  // (1, 1024)
    const float* mem   = (const float*)d_in[1];  // (1000, 50, 1024)
    const float* van   = (const float*)d_in[2];  // (1000, 1, 1024)
    const float* gb    = (const float*)d_in[3];  // (1000, 1024)
    const float* gbk   = (const float*)d_in[4];  // (1000, 1024)
    const float* gbv   = (const float*)d_in[5];  // (1000, 1024)
    const float* ffn   = (const float*)d_in[6];  // (1000, 1024)
    const float* scale = (const float*)d_in[7];  // scalar

    dualmem_kernel<<<GRID, 128>>>(mem, van, gbk, gbv, ffn, img, gb, scale,
                                  (float*)d_out);
}

// round 15
// speedup vs baseline: 1.6244x; 1.6244x over previous
#include <cuda_runtime.h>
#include <cstdint>
#include <math.h>

#define BETA  5.5f
#define NC    1000
#define NM    50
#define ND    1024
#define ND4   256
#define QB    40          // qn partial blocks
#define QROWS 25          // rows per block (40*25 = 1000)

__device__ __align__(16) float g_qn[ND];
__device__ float g_logits[NC];
__device__ float g_qpart[QB * ND];
__device__ __align__(16) float g_pacc[2 * NC * ND];   // per-half partial acc (8 MB)
__device__ float g_psw[2 * NC];
__device__ unsigned int g_tick[NC];                    // zero-init, self-resetting
__device__ unsigned int g_ctr_q = 0;
__device__ unsigned int g_ctr_m = 0;

// ---------------------------------------------------------------------------
// Kernel 1: qn = l2norm(img + mean(global_bias,0)). grid=40 x 1024, ticketed.
// (round-13 configuration)
// ---------------------------------------------------------------------------
__global__ void qn_kernel(const float* __restrict__ gb,
                          const float* __restrict__ img)
{
    const int d = threadIdx.x;
    const int b = blockIdx.x;
    const float* base = gb + (size_t)b * QROWS * ND + d;
    float s = 0.0f;
    #pragma unroll 5
    for (int r = 0; r < QROWS; ++r) s += base[r * ND];
    g_qpart[b * ND + d] = s;

    __shared__ unsigned int ticket;
    __threadfence();
    __syncthreads();
    if (d == 0) ticket = atomicAdd(&g_ctr_q, 1u);
    __syncthreads();
    if (ticket != QB - 1) return;

    float tsum = 0.0f;
    #pragma unroll 8
    for (int bb = 0; bb < QB; ++bb) tsum += g_qpart[bb * ND + d];
    const float q = img[d] + tsum * (1.0f / (float)NC);

    __shared__ float red[32];
    float v = q * q;
    #pragma unroll
    for (int o = 16; o; o >>= 1) v += __shfl_xor_sync(0xffffffffu, v, o);
    const int w = d >> 5, lane = d & 31;
    if (lane == 0) red[w] = v;
    __syncthreads();
    float tot = 0.0f;
    #pragma unroll
    for (int i = 0; i < 32; ++i) tot += red[i];

    g_qn[d] = q * rsqrtf(tot);
    if (d == 0) g_ctr_q = 0;     // reset for graph replay
}

// ---------------------------------------------------------------------------
// Kernel 2: per-class attention, SPLIT 2 CTAs per class (grid=2000).
// CTA (2c+h): warp wi handles rows m = 4h+wi, step 8 (row 50 = vanilla,
// 50%8=2 -> half 0, warp 2). Mainloop = round-3/13 proven optimum.
// First-arriving half writes 4KB partial acc + sw and exits (frees SM slot);
// second adds partner's partial and runs the epilogue. Last epilogue CTA
// runs the softmax.
// ---------------------------------------------------------------------------
__global__ void __launch_bounds__(128)
dualmem_main_kernel(const float* __restrict__ mem,
                    const float* __restrict__ van,
                    const float* __restrict__ gbk,
                    const float* __restrict__ gbv,
                    const float* __restrict__ ffn,
                    const float* __restrict__ img,
                    const float* __restrict__ scale,
                    float* __restrict__ out)
{
    const int c    = blockIdx.x >> 1;
    const int h    = blockIdx.x & 1;
    const int t    = threadIdx.x;       // 0..127
    const int wi   = t >> 5;
    const int lane = t & 31;

    __shared__ float4 qn_s[ND4];
    __shared__ float4 bk_s[ND4];
    __shared__ float4 bv_s[ND4];
    __shared__ float4 accs[4][ND4];
    __shared__ float  sw_s[4];
    __shared__ float4 redc[4];
    __shared__ float  red1[4];
    __shared__ float2 red2[4];
    __shared__ float  redm[4], reds[4];
    __shared__ unsigned int utick;

    const float4* qn4  = (const float4*)g_qn;
    const float4* gbk4 = (const float4*)(gbk + (size_t)c * ND);
    const float4* gbv4 = (const float4*)(gbv + (size_t)c * ND);
    const float4* mem4 = (const float4*)(mem + (size_t)c * NM * ND);
    const float4* van4 = (const float4*)(van + (size_t)c * ND);

    // --- prologue: stage qn/bk/bv to smem, per-class constants ---
    float pqk = 0.0f, pkk = 0.0f, pvv = 0.0f;
    #pragma unroll
    for (int r = 0; r < 2; ++r) {
        const int idx = t + r * 128;
        const float4 q = qn4[idx];
        const float4 k = gbk4[idx];
        const float4 v = gbv4[idx];
        qn_s[idx] = q; bk_s[idx] = k; bv_s[idx] = v;
        pqk += q.x*k.x + q.y*k.y + q.z*k.z + q.w*k.w;
        pkk += k.x*k.x + k.y*k.y + k.z*k.z + k.w*k.w;
        pvv += v.x*v.x + v.y*v.y + v.z*v.z + v.w*v.w;
    }
    #pragma unroll
    for (int o = 16; o; o >>= 1) {
        pqk += __shfl_xor_sync(0xffffffffu, pqk, o);
        pkk += __shfl_xor_sync(0xffffffffu, pkk, o);
        pvv += __shfl_xor_sync(0xffffffffu, pvv, o);
    }
    if (lane == 0) redc[wi] = make_float4(pqk, pkk, pvv, 0.0f);
    __syncthreads();
    float qk_c = 0.0f, kk_c = 0.0f, vv_c = 0.0f;
    #pragma unroll
    for (int i = 0; i < 4; ++i) {
        qk_c += redc[i].x; kk_c += redc[i].y; vv_c += redc[i].z;
    }

    // --- mainloop: warp wi handles rows m = 4h+wi, step 8 (50 = vanilla) ---
    float4 acc[8];
    #pragma unroll
    for (int j = 0; j < 8; ++j) acc[j] = make_float4(0.f, 0.f, 0.f, 0.f);
    float sw = 0.0f;

    float4 xr[8], xn[8];
    const int m_first = 4 * h + wi;          // 0..7, always <= NM
    {
        const float4* rp = (m_first < NM) ? (mem4 + (size_t)m_first * ND4) : van4;
        #pragma unroll
        for (int j = 0; j < 8; ++j) xr[j] = rp[j * 32 + lane];
    }

    int m = m_first;
    while (true) {
        const int  mn = m + 8;
        const bool hn = (mn <= NM);
        if (hn) {
            const float4* rq = (mn < NM) ? (mem4 + (size_t)mn * ND4) : van4;
            #pragma unroll
            for (int j = 0; j < 8; ++j) xn[j] = rq[j * 32 + lane];
        }

        float xx = 0.0f, qx = 0.0f, xk = 0.0f, xv = 0.0f;
        #pragma unroll
        for (int j = 0; j < 8; ++j) {
            const float4 x = xr[j];
            const float4 q = qn_s[j * 32 + lane];
            const float4 k = bk_s[j * 32 + lane];
            const float4 v = bv_s[j * 32 + lane];
            xx += x.x*x.x + x.y*x.y + x.z*x.z + x.w*x.w;
            qx += q.x*x.x + q.y*x.y + q.z*x.z + q.w*x.w;
            xk += k.x*x.x + k.y*x.y + k.z*x.z + k.w*x.w;
            xv += v.x*x.x + v.y*x.y + v.z*x.z + v.w*x.w;
        }
        #pragma unroll
        for (int o = 16; o; o >>= 1) {
            xx += __shfl_xor_sync(0xffffffffu, xx, o);
            qx += __shfl_xor_sync(0xffffffffu, qx, o);
            xk += __shfl_xor_sync(0xffffffffu, xk, o);
            xv += __shfl_xor_sync(0xffffffffu, xv, o);
        }

        float w = 0.0f;
        if (xx != 0.0f) {              // all-zero row <=> |x|^2 == 0
            const float dq = qx + qk_c;
            const float k2 = xx + 2.0f * xk + kk_c;
            const float v2 = xx + 2.0f * xv + vv_c;
            w = __expf(-BETA * (1.0f - dq * rsqrtf(k2))) * rsqrtf(v2);
        }
        sw += w;
        #pragma unroll
        for (int j = 0; j < 8; ++j) {
            acc[j].x += w * xr[j].x;
            acc[j].y += w * xr[j].y;
            acc[j].z += w * xr[j].z;
            acc[j].w += w * xr[j].w;
        }

        if (!hn) break;
        #pragma unroll
        for (int j = 0; j < 8; ++j) xr[j] = xn[j];
        m = mn;
    }

    // --- combine this CTA's 4 warps ---
    #pragma unroll
    for (int j = 0; j < 8; ++j) accs[wi][j * 32 + lane] = acc[j];
    if (lane == 0) sw_s[wi] = sw;
    __syncthreads();

    const float sw_own = sw_s[0] + sw_s[1] + sw_s[2] + sw_s[3];
    float4 p0, p1;                     // this CTA's partial acc at idx t, t+128
    {
        const int i0 = t, i1 = t + 128;
        float4 s0 = accs[0][i0], s1 = accs[0][i1];
        #pragma unroll
        for (int w = 1; w < 4; ++w) {
            const float4 p = accs[w][i0], q = accs[w][i1];
            s0.x += p.x; s0.y += p.y; s0.z += p.z; s0.w += p.w;
            s1.x += q.x; s1.y += q.y; s1.z += q.z; s1.w += q.w;
        }
        p0 = s0; p1 = s1;
    }

    // --- cross-CTA ticket: write own partial, bump; first exits ---
    float4* pac4 = (float4*)g_pacc + ((size_t)(2 * c + h)) * ND4;
    pac4[t] = p0;
    pac4[t + 128] = p1;
    if (t == 0) g_psw[2 * c + h] = sw_own;
    __threadfence();
    __syncthreads();
    if (t == 0) utick = atomicAdd(&g_tick[c], 1u);
    __syncthreads();
    if (utick == 0) return;            // first half done; slot freed

    // --- second arriver: combine with partner, epilogue ---
    __threadfence();                   // acquire partner's partials
    const float4* par4 = (const float4*)g_pacc + ((size_t)(2 * c + (1 - h))) * ND4;
    const float4 q0 = par4[t];
    const float4 q1 = par4[t + 128];
    const float swt = sw_own + g_psw[2 * c + (1 - h)];

    const float4 b0 = bv_s[t], b1 = bv_s[t + 128];
    const float4 a0 = make_float4(p0.x + q0.x + swt*b0.x, p0.y + q0.y + swt*b0.y,
                                  p0.z + q0.z + swt*b0.z, p0.w + q0.w + swt*b0.w);
    const float4 a1 = make_float4(p1.x + q1.x + swt*b1.x, p1.y + q1.y + swt*b1.y,
                                  p1.z + q1.z + swt*b1.z, p1.w + q1.w + swt*b1.w);

    // l2norm(acc)
    float n1 = a0.x*a0.x + a0.y*a0.y + a0.z*a0.z + a0.w*a0.w
             + a1.x*a1.x + a1.y*a1.y + a1.z*a1.z + a1.w*a1.w;
    #pragma unroll
    for (int o = 16; o; o >>= 1) n1 += __shfl_xor_sync(0xffffffffu, n1, o);
    if (lane == 0) red1[wi] = n1;
    __syncthreads();
    const float rin1 = rsqrtf(red1[0] + red1[1] + red1[2] + red1[3]);

    // + ffn, l2norm, dot img
    const float4* ffn4 = (const float4*)(ffn + (size_t)c * ND);
    const float4* img4 = (const float4*)img;
    const float4 f0 = ffn4[t], f1 = ffn4[t + 128];
    const float4 i0 = img4[t], i1 = img4[t + 128];
    const float4 af0 = make_float4(a0.x*rin1 + f0.x, a0.y*rin1 + f0.y,
                                   a0.z*rin1 + f0.z, a0.w*rin1 + f0.w);
    const float4 af1 = make_float4(a1.x*rin1 + f1.x, a1.y*rin1 + f1.y,
                                   a1.z*rin1 + f1.z, a1.w*rin1 + f1.w);

    float n2 = af0.x*af0.x + af0.y*af0.y + af0.z*af0.z + af0.w*af0.w
             + af1.x*af1.x + af1.y*af1.y + af1.z*af1.z + af1.w*af1.w;
    float dp = af0.x*i0.x + af0.y*i0.y + af0.z*i0.z + af0.w*i0.w
             + af1.x*i1.x + af1.y*i1.y + af1.z*i1.z + af1.w*i1.w;
    #pragma unroll
    for (int o = 16; o; o >>= 1) {
        n2 += __shfl_xor_sync(0xffffffffu, n2, o);
        dp += __shfl_xor_sync(0xffffffffu, dp, o);
    }
    if (lane == 0) red2[wi] = make_float2(n2, dp);
    __syncthreads();

    if (t == 0) {
        float n2t = 0.0f, dpt = 0.0f;
        #pragma unroll
        for (int i = 0; i < 4; ++i) { n2t += red2[i].x; dpt += red2[i].y; }
        g_logits[c] = expf(scale[0]) * dpt * rsqrtf(n2t);
        g_tick[c] = 0;                 // reset for graph replay (last user)
    }

    // --- last epilogue CTA: softmax over g_logits ---
    __threadfence();
    __syncthreads();
    if (t == 0) utick = atomicAdd(&g_ctr_m, 1u);
    __syncthreads();
    if (utick != NC - 1) return;

    float x[8];
    #pragma unroll
    for (int k = 0; k < 8; ++k) {
        const int i = t + k * 128;
        x[k] = (i < NC) ? g_logits[i] : -INFINITY;
    }
    float mx = x[0];
    #pragma unroll
    for (int k = 1; k < 8; ++k) mx = fmaxf(mx, x[k]);
    #pragma unroll
    for (int o = 16; o; o >>= 1) mx = fmaxf(mx, __shfl_xor_sync(0xffffffffu, mx, o));
    if (lane == 0) redm[wi] = mx;
    __syncthreads();
    mx = fmaxf(fmaxf(redm[0], redm[1]), fmaxf(redm[2], redm[3]));

    float e[8];
    float es = 0.0f;
    #pragma unroll
    for (int k = 0; k < 8; ++k) {
        const int i = t + k * 128;
        e[k] = (i < NC) ? expf(x[k] - mx) : 0.0f;
        es += e[k];
    }
    #pragma unroll
    for (int o = 16; o; o >>= 1) es += __shfl_xor_sync(0xffffffffu, es, o);
    if (lane == 0) reds[wi] = es;
    __syncthreads();
    const float rst = 1.0f / (reds[0] + reds[1] + reds[2] + reds[3]);

    #pragma unroll
    for (int k = 0; k < 8; ++k) {
        const int i = t + k * 128;
        if (i < NC) out[i] = e[k] * rst;
    }
    if (t == 0) g_ctr_m = 0;           // reset for graph replay
}

// ---------------------------------------------------------------------------
extern "C" void kernel_launch(void* const* d_in, const int* in_sizes, int n_in,
                              void* d_out, int out_size)
{
    const float* img   = (const float*)d_in[0];  // (1, 1024)
    const float* mem   = (const float*)d_in[1];  // (1000, 50, 1024)
    const float* van   = (const float*)d_in[2];  // (1000, 1, 1024)
    const float* gb    = (const float*)d_in[3];  // (1000, 1024)
    const float* gbk   = (const float*)d_in[4];  // (1000, 1024)
    const float* gbv   = (const float*)d_in[5];  // (1000, 1024)
    const float* ffn   = (const float*)d_in[6];  // (1000, 1024)
    const float* scale = (const float*)d_in[7];  // scalar

    qn_kernel<<<QB, 1024>>>(gb, img);
    dualmem_main_kernel<<<2 * NC, 128>>>(mem, van, gbk, gbv, ffn, img, scale,
                                         (float*)d_out);
}